// round 1
// baseline (speedup 1.0000x reference)
#include <cuda_runtime.h>

#define NN 4096
#define DD 128
#define NBLK 128
#define NTHR 512
#define NWARP (NTHR / 32)
#define REGC 0.05f
#define EPSC 1e-8f
#define NITER 100
#define MUNU (1.0f / 4096.0f)

// Scratch (allowed: __device__ globals, no runtime allocation)
__device__ float g_K[(size_t)NN * NN];   // 67 MB, fits in L2
__device__ float g_u[NN];
__device__ float g_v[NN];
__device__ float g_xsq[NN];
__device__ float g_ysq[NN];
__device__ double g_loss;
__device__ unsigned int g_bar_count;     // zero-init, returns to 0 each barrier
__device__ volatile unsigned int g_bar_gen;

// Software grid barrier for a fully-resident persistent grid.
// __threadfence() is gpu-scope => CCTL.IVALL on sm_103a => L1 invalidated,
// so post-barrier loads observe other CTAs' writes.
__device__ __forceinline__ void grid_barrier() {
    __syncthreads();
    if (threadIdx.x == 0) {
        __threadfence();
        unsigned int gen = g_bar_gen;
        if (atomicAdd(&g_bar_count, 1u) == (unsigned)(gridDim.x - 1)) {
            g_bar_count = 0;
            __threadfence();
            g_bar_gen = gen + 1;
        } else {
            while (g_bar_gen == gen) __nanosleep(64);
        }
        __threadfence();
    }
    __syncthreads();
}

__global__ __launch_bounds__(NTHR, 1) void ot_kernel(
    const float* __restrict__ z0, const float* __restrict__ z1,
    const float* __restrict__ z2, float* __restrict__ out)
{
    // GEMM phase uses s_mem as sxT[32][132] + syT[32][68] (k-transposed tiles).
    // Pass phases reuse s_mem as a 4096-float u/v cache.
    __shared__ __align__(16) float s_mem[6400];
    __shared__ float s_red[NTHR];
    __shared__ double s_dacc[NWARP];

    const int tid  = threadIdx.x;
    const int bid  = blockIdx.x;
    const int wid  = tid >> 5;
    const int lane = tid & 31;

    if (bid == 0 && tid == 0) g_loss = 0.0;  // reset every launch (graph replays)

    const float* Xs[3] = { z0, z0, z1 };
    const float* Ys[3] = { z1, z2, z2 };

    for (int p = 0; p < 3; ++p) {
        const float* x = Xs[p];
        const float* y = Ys[p];

        // ---------- Phase 1: row norms + u init ----------
        {
            int gw = bid * NWARP + wid;                 // 0..2047
            for (int r = gw; r < 2 * NN; r += NBLK * NWARP) {
                const float* src = (r < NN) ? x : y;
                int row = (r < NN) ? r : (r - NN);
                const float4* rp = (const float4*)(src + (size_t)row * DD);
                float4 v4 = rp[lane];                   // 128 floats = 32 float4
                float s = v4.x * v4.x + v4.y * v4.y + v4.z * v4.z + v4.w * v4.w;
                #pragma unroll
                for (int o = 16; o; o >>= 1) s += __shfl_xor_sync(0xffffffffu, s, o);
                if (lane == 0) { if (r < NN) g_xsq[row] = s; else g_ysq[row] = s; }
            }
            for (int i = bid * NTHR + tid; i < NN; i += NBLK * NTHR) g_u[i] = 1.0f;
        }
        grid_barrier();

        // ---------- Phase 2: build K = exp(-C/REG), C = clip(|x|^2+|y|^2-2x.y, 0) ----------
        {
            float* sxT = s_mem;                 // [32 k][128 i], stride 132
            float* syT = s_mem + 32 * 132;      // [32 k][64  j], stride 68
            const int ty = tid >> 4;            // 0..31 -> 4 rows each (128-row tile)
            const int tx = tid & 15;            // 0..15 -> 4 cols each (64-col tile)
            const int NT = (NN / 128) * (NN / 64);   // 2048 tiles

            for (int t = bid; t < NT; t += NBLK) {
                const int r0 = (t / 64) * 128;
                const int c0 = (t % 64) * 64;
                float acc[4][4];
                #pragma unroll
                for (int m = 0; m < 4; ++m)
                    #pragma unroll
                    for (int n = 0; n < 4; ++n) acc[m][n] = 0.f;

                for (int kc = 0; kc < DD; kc += 32) {
                    __syncthreads();
                    #pragma unroll
                    for (int idx = tid; idx < 128 * 32; idx += NTHR) {
                        int rr = idx >> 5, cc = idx & 31;
                        sxT[cc * 132 + rr] = x[(size_t)(r0 + rr) * DD + kc + cc];
                    }
                    #pragma unroll
                    for (int idx = tid; idx < 64 * 32; idx += NTHR) {
                        int rr = idx >> 5, cc = idx & 31;
                        syT[cc * 68 + rr] = y[(size_t)(c0 + rr) * DD + kc + cc];
                    }
                    __syncthreads();
                    #pragma unroll 8
                    for (int k = 0; k < 32; ++k) {
                        float4 a4 = *(const float4*)&sxT[k * 132 + ty * 4];
                        float4 b4 = *(const float4*)&syT[k * 68 + tx * 4];
                        acc[0][0] += a4.x * b4.x; acc[0][1] += a4.x * b4.y;
                        acc[0][2] += a4.x * b4.z; acc[0][3] += a4.x * b4.w;
                        acc[1][0] += a4.y * b4.x; acc[1][1] += a4.y * b4.y;
                        acc[1][2] += a4.y * b4.z; acc[1][3] += a4.y * b4.w;
                        acc[2][0] += a4.z * b4.x; acc[2][1] += a4.z * b4.y;
                        acc[2][2] += a4.z * b4.z; acc[2][3] += a4.z * b4.w;
                        acc[3][0] += a4.w * b4.x; acc[3][1] += a4.w * b4.y;
                        acc[3][2] += a4.w * b4.z; acc[3][3] += a4.w * b4.w;
                    }
                }

                const int j0 = c0 + tx * 4;
                #pragma unroll
                for (int m = 0; m < 4; ++m) {
                    int i = r0 + ty * 4 + m;
                    float xs = g_xsq[i];
                    float4 o;
                    float C0 = fmaxf(xs + g_ysq[j0 + 0] - 2.f * acc[m][0], 0.f);
                    float C1 = fmaxf(xs + g_ysq[j0 + 1] - 2.f * acc[m][1], 0.f);
                    float C2 = fmaxf(xs + g_ysq[j0 + 2] - 2.f * acc[m][2], 0.f);
                    float C3 = fmaxf(xs + g_ysq[j0 + 3] - 2.f * acc[m][3], 0.f);
                    o.x = __expf(-C0 * (1.0f / REGC));
                    o.y = __expf(-C1 * (1.0f / REGC));
                    o.z = __expf(-C2 * (1.0f / REGC));
                    o.w = __expf(-C3 * (1.0f / REGC));
                    *(float4*)(g_K + (size_t)i * NN + j0) = o;
                }
            }
        }
        grid_barrier();

        // ---------- Phase 3: 100 Sinkhorn iterations ----------
        for (int it = 0; it < NITER; ++it) {
            // column pass: v[j] = nu / (sum_i K[i][j] u[i] + eps)
            {
                float* u_s = s_mem;
                for (int i = tid; i < NN; i += NTHR) u_s[i] = g_u[i];
                __syncthreads();
                const int j = (bid << 5) + lane;            // 32 cols per CTA
                const float* kp = g_K + (size_t)wid * NN + j;
                float acc = 0.f;
                #pragma unroll 16
                for (int i = wid; i < NN; i += NWARP) {
                    acc += (*kp) * u_s[i];
                    kp += (size_t)NWARP * NN;
                }
                s_red[tid] = acc;
                __syncthreads();
                if (wid == 0) {
                    float s = 0.f;
                    #pragma unroll
                    for (int w = 0; w < NWARP; ++w) s += s_red[w * 32 + lane];
                    g_v[j] = MUNU / (s + EPSC);
                }
            }
            grid_barrier();
            // row pass: u[i] = mu / (sum_j K[i][j] v[j] + eps)
            {
                float* v_s = s_mem;
                for (int i = tid; i < NN; i += NTHR) v_s[i] = g_v[i];
                __syncthreads();
                const int i0 = bid << 5;                    // 32 rows per CTA
                const float4* v4 = (const float4*)v_s;
                #pragma unroll
                for (int r = 0; r < 2; ++r) {
                    int row = i0 + wid * 2 + r;
                    const float4* kp4 = (const float4*)(g_K + (size_t)row * NN);
                    float acc = 0.f;
                    #pragma unroll 8
                    for (int j = lane; j < NN / 4; j += 32) {
                        float4 kv = kp4[j];
                        float4 vv = v4[j];
                        acc += kv.x * vv.x + kv.y * vv.y + kv.z * vv.z + kv.w * vv.w;
                    }
                    #pragma unroll
                    for (int o = 16; o; o >>= 1) acc += __shfl_xor_sync(0xffffffffu, acc, o);
                    if (lane == 0) g_u[row] = MUNU / (acc + EPSC);
                }
            }
            grid_barrier();
        }

        // ---------- Phase 4: loss += sum u_i K_ij v_j * (-REG * ln K_ij) ----------
        {
            float* v_s = s_mem;
            for (int i = tid; i < NN; i += NTHR) v_s[i] = g_v[i];
            __syncthreads();
            const int i0 = bid << 5;
            double wacc = 0.0;
            #pragma unroll
            for (int r = 0; r < 2; ++r) {
                int row = i0 + wid * 2 + r;
                const float* kp = g_K + (size_t)row * NN;
                float acc = 0.f;
                #pragma unroll 4
                for (int j = lane; j < NN; j += 32) {
                    float kk = kp[j];
                    acc += kk * v_s[j] * __logf(kk);
                }
                #pragma unroll
                for (int o = 16; o; o >>= 1) acc += __shfl_xor_sync(0xffffffffu, acc, o);
                if (lane == 0) wacc += (double)g_u[row] * (double)acc;
            }
            if (lane == 0) s_dacc[wid] = wacc;
            __syncthreads();
            if (tid == 0) {
                double c = 0.0;
                for (int w = 0; w < NWARP; ++w) c += s_dacc[w];
                atomicAdd(&g_loss, (double)(-REGC) * c);
            }
        }
        grid_barrier();   // protect g_K before next pair overwrites it
    }

    if (bid == 0 && tid == 0) out[0] = (float)(g_loss / 3.0);
}

extern "C" void kernel_launch(void* const* d_in, const int* in_sizes, int n_in,
                              void* d_out, int out_size) {
    (void)in_sizes; (void)n_in; (void)out_size;
    const float* z0 = (const float*)d_in[0];
    const float* z1 = (const float*)d_in[1];
    const float* z2 = (const float*)d_in[2];
    ot_kernel<<<NBLK, NTHR>>>(z0, z1, z2, (float*)d_out);
}

// round 2
// speedup vs baseline: 1.3010x; 1.3010x over previous
#include <cuda_runtime.h>
#include <cuda_bf16.h>

#define NN 4096
#define DD 128
#define NBLK 128
#define NTHR 512
#define NWARP (NTHR / 32)
#define REGC 0.05f
#define EPSC 1e-8f
#define NITER 100
#define MUNU (1.0f / 4096.0f)

// Scratch (__device__ globals — sanctioned, no runtime allocation)
__device__ float g_K32[(size_t)NN * NN];            // exact K, streamed (phase 4 only)
__device__ __nv_bfloat16 g_Kb [(size_t)NN * NN];    // bf16 K row-major  (row pass)
__device__ __nv_bfloat16 g_KbT[(size_t)NN * NN];    // bf16 K col-major  (col pass)
__device__ float g_u[NN];
__device__ float g_v[NN];
__device__ float g_xsq[NN];
__device__ float g_ysq[NN];
__device__ double g_loss;
__device__ unsigned int g_bar_count;
__device__ volatile unsigned int g_bar_gen;

__device__ __forceinline__ float bf_lo(unsigned int u) {
    return __uint_as_float(u << 16);
}
__device__ __forceinline__ float bf_hi(unsigned int u) {
    return __uint_as_float(u & 0xffff0000u);
}

// Software grid barrier (fully-resident persistent grid).
// __threadfence() is gpu-scope => CCTL.IVALL on sm_103a => post-barrier loads
// observe other CTAs' writes.
__device__ __forceinline__ void grid_barrier() {
    __syncthreads();
    if (threadIdx.x == 0) {
        __threadfence();
        unsigned int gen = g_bar_gen;
        if (atomicAdd(&g_bar_count, 1u) == (unsigned)(gridDim.x - 1)) {
            g_bar_count = 0;
            __threadfence();
            g_bar_gen = gen + 1;
        } else {
            while (g_bar_gen == gen) { }
        }
        __threadfence();
    }
    __syncthreads();
}

// One Sinkhorn half-step: out[r] = MUNU / (dot(M[r,:], in_s) + EPS)
// M is bf16, 4096 per row. 2 rows per warp, shared v/u vector in in_s.
__device__ __forceinline__ void half_step(
    const __nv_bfloat16* __restrict__ M,
    const float* __restrict__ in_g,
    float* __restrict__ out_g,
    float* in_s, int tid, int bid, int wid, int lane)
{
    for (int i = tid; i < NN; i += NTHR) in_s[i] = in_g[i];
    __syncthreads();

    const int row0 = (bid << 5) + (wid << 1);
    const uint2* k0 = (const uint2*)(M + (size_t)row0 * NN);
    const uint2* k1 = (const uint2*)(M + (size_t)(row0 + 1) * NN);
    const float4* v4 = (const float4*)in_s;

    float a0 = 0.f, a1 = 0.f;
    #pragma unroll 8
    for (int j = lane; j < NN / 4; j += 32) {
        uint2 p0 = k0[j];
        uint2 p1 = k1[j];
        float4 vv = v4[j];
        a0 += bf_lo(p0.x) * vv.x + bf_hi(p0.x) * vv.y
            + bf_lo(p0.y) * vv.z + bf_hi(p0.y) * vv.w;
        a1 += bf_lo(p1.x) * vv.x + bf_hi(p1.x) * vv.y
            + bf_lo(p1.y) * vv.z + bf_hi(p1.y) * vv.w;
    }
    #pragma unroll
    for (int o = 16; o; o >>= 1) {
        a0 += __shfl_xor_sync(0xffffffffu, a0, o);
        a1 += __shfl_xor_sync(0xffffffffu, a1, o);
    }
    if (lane == 0) {
        out_g[row0]     = MUNU / (a0 + EPSC);
        out_g[row0 + 1] = MUNU / (a1 + EPSC);
    }
    __syncthreads();   // in_s reused next half-step
}

__global__ __launch_bounds__(NTHR, 1) void ot_kernel(
    const float* __restrict__ z0, const float* __restrict__ z1,
    const float* __restrict__ z2, float* __restrict__ out)
{
    // GEMM phase: sxT[32][132] + syT[32][68]. Pass phases: 4096-float vector.
    __shared__ __align__(16) float s_mem[6400];
    __shared__ double s_dacc[NWARP];

    const int tid  = threadIdx.x;
    const int bid  = blockIdx.x;
    const int wid  = tid >> 5;
    const int lane = tid & 31;

    if (bid == 0 && tid == 0) g_loss = 0.0;   // reset each graph replay

    const float* Xs[3] = { z0, z0, z1 };
    const float* Ys[3] = { z1, z2, z2 };

    for (int p = 0; p < 3; ++p) {
        const float* x = Xs[p];
        const float* y = Ys[p];

        // ---------- Phase 1: row norms + u init ----------
        {
            int gw = bid * NWARP + wid;
            for (int r = gw; r < 2 * NN; r += NBLK * NWARP) {
                const float* src = (r < NN) ? x : y;
                int row = (r < NN) ? r : (r - NN);
                const float4* rp = (const float4*)(src + (size_t)row * DD);
                float4 v4 = rp[lane];
                float s = v4.x * v4.x + v4.y * v4.y + v4.z * v4.z + v4.w * v4.w;
                #pragma unroll
                for (int o = 16; o; o >>= 1) s += __shfl_xor_sync(0xffffffffu, s, o);
                if (lane == 0) { if (r < NN) g_xsq[row] = s; else g_ysq[row] = s; }
            }
            for (int i = bid * NTHR + tid; i < NN; i += NBLK * NTHR) g_u[i] = 1.0f;
        }
        grid_barrier();

        // ---------- Phase 2: K = exp(-C/REG); write K32 (stream), Kb, KbT ----------
        {
            float* sxT = s_mem;                 // [32 k][128 i], stride 132
            float* syT = s_mem + 32 * 132;      // [32 k][64  j], stride 68
            const int ty = tid >> 4;            // 0..31
            const int tx = tid & 15;            // 0..15
            const int NT = (NN / 128) * (NN / 64);   // 2048 tiles

            for (int t = bid; t < NT; t += NBLK) {
                const int r0 = (t / 64) * 128;
                const int c0 = (t % 64) * 64;
                float acc[4][4];
                #pragma unroll
                for (int m = 0; m < 4; ++m)
                    #pragma unroll
                    for (int n = 0; n < 4; ++n) acc[m][n] = 0.f;

                for (int kc = 0; kc < DD; kc += 32) {
                    __syncthreads();
                    #pragma unroll
                    for (int idx = tid; idx < 128 * 32; idx += NTHR) {
                        int rr = idx >> 5, cc = idx & 31;
                        sxT[cc * 132 + rr] = x[(size_t)(r0 + rr) * DD + kc + cc];
                    }
                    #pragma unroll
                    for (int idx = tid; idx < 64 * 32; idx += NTHR) {
                        int rr = idx >> 5, cc = idx & 31;
                        syT[cc * 68 + rr] = y[(size_t)(c0 + rr) * DD + kc + cc];
                    }
                    __syncthreads();
                    #pragma unroll 8
                    for (int k = 0; k < 32; ++k) {
                        float4 a4 = *(const float4*)&sxT[k * 132 + ty * 4];
                        float4 b4 = *(const float4*)&syT[k * 68 + tx * 4];
                        acc[0][0] += a4.x * b4.x; acc[0][1] += a4.x * b4.y;
                        acc[0][2] += a4.x * b4.z; acc[0][3] += a4.x * b4.w;
                        acc[1][0] += a4.y * b4.x; acc[1][1] += a4.y * b4.y;
                        acc[1][2] += a4.y * b4.z; acc[1][3] += a4.y * b4.w;
                        acc[2][0] += a4.z * b4.x; acc[2][1] += a4.z * b4.y;
                        acc[2][2] += a4.z * b4.z; acc[2][3] += a4.z * b4.w;
                        acc[3][0] += a4.w * b4.x; acc[3][1] += a4.w * b4.y;
                        acc[3][2] += a4.w * b4.z; acc[3][3] += a4.w * b4.w;
                    }
                }

                const int j0 = c0 + tx * 4;
                const int i0 = r0 + ty * 4;
                float e[4][4];
                #pragma unroll
                for (int m = 0; m < 4; ++m) {
                    float xs = g_xsq[i0 + m];
                    #pragma unroll
                    for (int n = 0; n < 4; ++n) {
                        float C = fmaxf(xs + g_ysq[j0 + n] - 2.f * acc[m][n], 0.f);
                        e[m][n] = __expf(-C * (1.0f / REGC));
                    }
                    float4 o4 = make_float4(e[m][0], e[m][1], e[m][2], e[m][3]);
                    __stcs((float4*)(g_K32 + (size_t)(i0 + m) * NN + j0), o4);
                    __nv_bfloat162 b01 = __floats2bfloat162_rn(e[m][0], e[m][1]);
                    __nv_bfloat162 b23 = __floats2bfloat162_rn(e[m][2], e[m][3]);
                    uint2 pk;
                    pk.x = *(unsigned int*)&b01;
                    pk.y = *(unsigned int*)&b23;
                    *(uint2*)(g_Kb + (size_t)(i0 + m) * NN + j0) = pk;
                }
                // transposed copy: KbT[j][i0..i0+3]
                #pragma unroll
                for (int n = 0; n < 4; ++n) {
                    __nv_bfloat162 b01 = __floats2bfloat162_rn(e[0][n], e[1][n]);
                    __nv_bfloat162 b23 = __floats2bfloat162_rn(e[2][n], e[3][n]);
                    uint2 pk;
                    pk.x = *(unsigned int*)&b01;
                    pk.y = *(unsigned int*)&b23;
                    *(uint2*)(g_KbT + (size_t)(j0 + n) * NN + i0) = pk;
                }
            }
        }
        grid_barrier();

        // ---------- Phase 3: 100 Sinkhorn iterations ----------
        for (int it = 0; it < NITER; ++it) {
            // v[j] = nu / (K^T u)[j]  — rows of KbT
            half_step(g_KbT, g_u, g_v, s_mem, tid, bid, wid, lane);
            grid_barrier();
            // u[i] = mu / (K v)[i]    — rows of Kb
            half_step(g_Kb, g_v, g_u, s_mem, tid, bid, wid, lane);
            grid_barrier();
        }

        // ---------- Phase 4: loss += sum u_i K_ij v_j * (-REG * ln K_ij) (exact K32) ----------
        {
            float* v_s = s_mem;
            for (int i = tid; i < NN; i += NTHR) v_s[i] = g_v[i];
            __syncthreads();
            const int i0 = bid << 5;
            double wacc = 0.0;
            #pragma unroll
            for (int r = 0; r < 2; ++r) {
                int row = i0 + wid * 2 + r;
                const float4* kp4 = (const float4*)(g_K32 + (size_t)row * NN);
                const float4* v4 = (const float4*)v_s;
                float acc = 0.f;
                #pragma unroll 4
                for (int j = lane; j < NN / 4; j += 32) {
                    float4 kk = __ldcs(kp4 + j);
                    float4 vv = v4[j];
                    acc += kk.x * vv.x * __logf(kk.x);
                    acc += kk.y * vv.y * __logf(kk.y);
                    acc += kk.z * vv.z * __logf(kk.z);
                    acc += kk.w * vv.w * __logf(kk.w);
                }
                #pragma unroll
                for (int o = 16; o; o >>= 1) acc += __shfl_xor_sync(0xffffffffu, acc, o);
                if (lane == 0) wacc += (double)g_u[row] * (double)acc;
            }
            if (lane == 0) s_dacc[wid] = wacc;
            __syncthreads();
            if (tid == 0) {
                double c = 0.0;
                for (int w = 0; w < NWARP; ++w) c += s_dacc[w];
                atomicAdd(&g_loss, (double)(-REGC) * c);
            }
        }
        grid_barrier();   // protect K buffers before next pair overwrites them
    }

    if (bid == 0 && tid == 0) out[0] = (float)(g_loss / 3.0);
}

extern "C" void kernel_launch(void* const* d_in, const int* in_sizes, int n_in,
                              void* d_out, int out_size) {
    (void)in_sizes; (void)n_in; (void)out_size;
    const float* z0 = (const float*)d_in[0];
    const float* z1 = (const float*)d_in[1];
    const float* z2 = (const float*)d_in[2];
    ot_kernel<<<NBLK, NTHR>>>(z0, z1, z2, (float*)d_out);
}